// round 1
// baseline (speedup 1.0000x reference)
#include <cuda_runtime.h>
#include <math.h>

#define NMAX 20000
#define HDIM 256
#define GNUM 64

// ---------------- scratch (device globals, no allocation) ----------------
__device__ float g_deg_out[NMAX];
__device__ float g_deg_in[NMAX];
__device__ float g_hn[NMAX * HDIM];    // (h * D_out^-1/2) @ W_conv
__device__ float g_agg[NMAX * HDIM];   // scatter target, then becomes hr in place
__device__ float g_gate[NMAX];
__device__ int   g_counts[GNUM];
__device__ int   g_starts[GNUM + 1];

// ---------------- init: zero scratch ----------------
__global__ void k_init(int Nn) {
    int i = blockIdx.x * blockDim.x + threadIdx.x;
    int total = Nn * HDIM;
    for (int idx = i; idx < total; idx += gridDim.x * blockDim.x)
        g_agg[idx] = 0.0f;
    if (i < Nn) { g_deg_out[i] = 0.0f; g_deg_in[i] = 0.0f; }
    if (i < GNUM) g_counts[i] = 0;
}

// ---------------- degrees ----------------
__global__ void k_deg(const int* __restrict__ src, const int* __restrict__ dst, int E) {
    int e = blockIdx.x * blockDim.x + threadIdx.x;
    if (e < E) {
        atomicAdd(&g_deg_out[src[e]], 1.0f);
        atomicAdd(&g_deg_in[dst[e]], 1.0f);
    }
}

// ---------------- graph-id counts (graph_id is sorted) ----------------
__global__ void k_count(const int* __restrict__ gid, int Nn) {
    int n = blockIdx.x * blockDim.x + threadIdx.x;
    if (n < Nn) atomicAdd(&g_counts[gid[n]], 1);
}

__global__ void k_scan() {
    if (threadIdx.x == 0) {
        int s = 0;
        for (int g = 0; g < GNUM; g++) { g_starts[g] = s; s += g_counts[g]; }
        g_starts[GNUM] = s;
    }
}

// ---------------- GEMM: hn = (h * rsqrt(max(deg_out,1))) @ W_conv ----------------
// 64x64 tile, BK=16, 256 threads, 4x4 micro-tile
__global__ void k_gemm_hn(const float* __restrict__ h, const float* __restrict__ W,
                          int M) {
    __shared__ float As[16][64];
    __shared__ float Bs[16][64];
    int tid = threadIdx.x;
    int tx = tid % 16, ty = tid / 16;
    int m0 = blockIdx.y * 64;
    int n0 = blockIdx.x * 64;

    int a_m = tid / 4;             // row within tile 0..63
    int a_k4 = (tid % 4) * 4;      // k offset 0,4,8,12
    int b_k = tid / 16;            // 0..15
    int b_n = (tid % 16) * 4;      // 0..60

    int gm = m0 + a_m;
    float scale = 0.0f;
    if (gm < M) scale = rsqrtf(fmaxf(g_deg_out[gm], 1.0f));

    float acc[4][4];
#pragma unroll
    for (int i = 0; i < 4; i++)
#pragma unroll
        for (int j = 0; j < 4; j++) acc[i][j] = 0.0f;

    for (int k0 = 0; k0 < HDIM; k0 += 16) {
        float4 av = make_float4(0.f, 0.f, 0.f, 0.f);
        if (gm < M)
            av = *reinterpret_cast<const float4*>(h + (size_t)gm * HDIM + k0 + a_k4);
        As[a_k4 + 0][a_m] = av.x * scale;
        As[a_k4 + 1][a_m] = av.y * scale;
        As[a_k4 + 2][a_m] = av.z * scale;
        As[a_k4 + 3][a_m] = av.w * scale;

        float4 bv = *reinterpret_cast<const float4*>(W + (size_t)(k0 + b_k) * HDIM + n0 + b_n);
        *reinterpret_cast<float4*>(&Bs[b_k][b_n]) = bv;
        __syncthreads();

#pragma unroll
        for (int kk = 0; kk < 16; kk++) {
            float a[4], b[4];
#pragma unroll
            for (int i = 0; i < 4; i++) a[i] = As[kk][ty * 4 + i];
#pragma unroll
            for (int j = 0; j < 4; j++) b[j] = Bs[kk][tx * 4 + j];
#pragma unroll
            for (int i = 0; i < 4; i++)
#pragma unroll
                for (int j = 0; j < 4; j++) acc[i][j] += a[i] * b[j];
        }
        __syncthreads();
    }

#pragma unroll
    for (int i = 0; i < 4; i++) {
        int m = m0 + ty * 4 + i;
        if (m < M) {
            float4 v = make_float4(acc[i][0], acc[i][1], acc[i][2], acc[i][3]);
            *reinterpret_cast<float4*>(g_hn + (size_t)m * HDIM + n0 + tx * 4) = v;
        }
    }
}

// ---------------- edge scatter-add: agg[dst] += hn[src] ----------------
// one warp per edge, 8 features per lane
__global__ void k_scatter(const int* __restrict__ src, const int* __restrict__ dst, int E) {
    int e = blockIdx.x * 8 + (threadIdx.x >> 5);
    if (e >= E) return;
    int lane = threadIdx.x & 31;
    int s = src[e];
    int d = dst[e];
    const float* srow = g_hn + (size_t)s * HDIM;
    float* drow = g_agg + (size_t)d * HDIM;
#pragma unroll
    for (int i = 0; i < 8; i++) {
        int f = lane + i * 32;
        atomicAdd(drow + f, __ldg(srow + f));
    }
}

// ---------------- per-node finish: scale, bias, relu, gate score ----------------
__global__ void k_node_finish(const float* __restrict__ b_conv,
                              const float* __restrict__ w_gate,
                              const float* __restrict__ b_gate) {
    int n = blockIdx.x;
    int f = threadIdx.x;
    __shared__ float red[256];
    float sc = rsqrtf(fmaxf(g_deg_in[n], 1.0f));
    float v = g_agg[(size_t)n * HDIM + f] * sc + b_conv[f];
    v = fmaxf(v, 0.0f);
    g_agg[(size_t)n * HDIM + f] = v;   // hr in place
    red[f] = v * w_gate[f];
    __syncthreads();
#pragma unroll
    for (int st = 128; st > 0; st >>= 1) {
        if (f < st) red[f] += red[f + st];
        __syncthreads();
    }
    if (f == 0) g_gate[n] = red[0] + b_gate[0];
}

// ---------------- per-graph pooling: segment softmax + weighted sum ----------------
__global__ void k_pool(float* __restrict__ att_out, float* __restrict__ hg_out) {
    int g = blockIdx.x;
    int s = g_starts[g], e = g_starts[g + 1];
    int tid = threadIdx.x;
    __shared__ float red[256];

    if (s >= e) {                 // empty graph: hg = 0
        hg_out[(size_t)g * HDIM + tid] = 0.0f;
        return;
    }
    // max
    float m = -INFINITY;
    for (int n = s + tid; n < e; n += 256) m = fmaxf(m, g_gate[n]);
    red[tid] = m; __syncthreads();
#pragma unroll
    for (int st = 128; st > 0; st >>= 1) {
        if (tid < st) red[tid] = fmaxf(red[tid], red[tid + st]);
        __syncthreads();
    }
    float gm = red[0];
    __syncthreads();
    // exp + sum, stash unnormalized e in att_out
    float sm = 0.0f;
    for (int n = s + tid; n < e; n += 256) {
        float ev = __expf(g_gate[n] - gm);
        att_out[n] = ev;
        sm += ev;
    }
    red[tid] = sm; __syncthreads();
#pragma unroll
    for (int st = 128; st > 0; st >>= 1) {
        if (tid < st) red[tid] += red[tid + st];
        __syncthreads();
    }
    float inv = 1.0f / red[0];
    __syncthreads();
    // weighted sum: thread owns feature tid
    float acc = 0.0f;
    for (int n = s; n < e; n++) {
        float a = att_out[n] * inv;           // uniform broadcast load
        acc += a * g_agg[(size_t)n * HDIM + tid];
    }
    hg_out[(size_t)g * HDIM + tid] = acc;
    __syncthreads();
    // normalize att in place
    for (int n = s + tid; n < e; n += 256) att_out[n] *= inv;
}

// ---------------- classifier heads: sigmoid(relu-free (hg@W1+b1)@W2 + b2) ----------------
__global__ void k_heads(const float* __restrict__ hg,
                        const float* __restrict__ W1, const float* __restrict__ b1,
                        const float* __restrict__ W2, const float* __restrict__ b2,
                        float* __restrict__ probs) {
    int g = blockIdx.x;
    int j = threadIdx.x;
    __shared__ float s_hg[256];
    __shared__ float r0[256], r1[256];
    s_hg[j] = hg[(size_t)g * HDIM + j];
    __syncthreads();
    float acc = b1[j];
#pragma unroll 8
    for (int k = 0; k < HDIM; k++) acc += s_hg[k] * W1[(size_t)k * HDIM + j];
    // a3 partials
    r0[j] = acc * W2[j * 2 + 0];
    r1[j] = acc * W2[j * 2 + 1];
    __syncthreads();
#pragma unroll
    for (int st = 128; st > 0; st >>= 1) {
        if (j < st) { r0[j] += r0[j + st]; r1[j] += r1[j + st]; }
        __syncthreads();
    }
    if (j == 0) {
        probs[g * 2 + 0] = 1.0f / (1.0f + expf(-(r0[0] + b2[0])));
        probs[g * 2 + 1] = 1.0f / (1.0f + expf(-(r1[0] + b2[1])));
    }
}

// ---------------- launch ----------------
extern "C" void kernel_launch(void* const* d_in, const int* in_sizes, int n_in,
                              void* d_out, int out_size) {
    const float* h      = (const float*)d_in[0];
    const int*   src    = (const int*)d_in[1];
    const int*   dst    = (const int*)d_in[2];
    const int*   gid    = (const int*)d_in[3];
    const float* W_conv = (const float*)d_in[4];
    const float* b_conv = (const float*)d_in[5];
    const float* w_gate = (const float*)d_in[6];
    const float* b_gate = (const float*)d_in[7];
    const float* W1     = (const float*)d_in[8];
    const float* b1     = (const float*)d_in[9];
    const float* W2     = (const float*)d_in[10];
    const float* b2     = (const float*)d_in[11];

    int Nn = in_sizes[3];   // graph_id element count
    int E  = in_sizes[1];   // src element count

    float* out   = (float*)d_out;
    float* probs = out;                       // [G*2]
    float* att   = out + GNUM * 2;            // [N]
    float* hg    = out + GNUM * 2 + Nn;       // [G*H]

    k_init<<<4096, 256>>>(Nn);
    k_deg<<<(E + 255) / 256, 256>>>(src, dst, E);
    k_count<<<(Nn + 255) / 256, 256>>>(gid, Nn);
    k_scan<<<1, 64>>>();
    dim3 gg(HDIM / 64, (Nn + 63) / 64);
    k_gemm_hn<<<gg, 256>>>(h, W_conv, Nn);
    k_scatter<<<(E + 7) / 8, 256>>>(src, dst, E);
    k_node_finish<<<Nn, 256>>>(b_conv, w_gate, b_gate);
    k_pool<<<GNUM, 256>>>(att, hg);
    k_heads<<<GNUM, 256>>>(hg, W1, b1, W2, b2, probs);
}